// round 2
// baseline (speedup 1.0000x reference)
#include <cuda_runtime.h>
#include <cstddef>

#define DIM 64
#define MAX_NODES 100000
#define NODES_PER_BLOCK 16

// Scratch aggregate buffer. __device__ globals are zero-initialized at module
// load, and the MLP kernel re-zeroes every element it reads, so the buffer is
// all-zero again at the end of every kernel_launch invocation (graph-replay safe).
__device__ float g_agg[(size_t)MAX_NODES * DIM];

// ---------------------------------------------------------------------------
// Kernel 1: edge scatter-add.  One thread per (edge, 16B chunk): 16 threads/edge.
// x[src] rows are 256B and hit L2 (x = 25.6MB < 126MB L2). The adds go through
// the L2 atomic ALUs via vector red (4 floats / op).
// ---------------------------------------------------------------------------
__global__ void __launch_bounds__(256) gin_scatter_kernel(
    const int* __restrict__ edge_index,   // [2, E] flat: src = [0,E), dst = [E,2E)
    const float* __restrict__ x,
    int n_edges)
{
    int gid = blockIdx.x * blockDim.x + threadIdx.x;
    int e = gid >> 4;
    if (e >= n_edges) return;
    int c = gid & 15;

    int src = __ldg(edge_index + e);
    int dst = __ldg(edge_index + n_edges + e);

    const float4 v = *reinterpret_cast<const float4*>(x + (size_t)src * DIM + c * 4);
    float* p = g_agg + (size_t)dst * DIM + c * 4;
    asm volatile("red.global.add.v4.f32 [%0], {%1, %2, %3, %4};"
                 :: "l"(p), "f"(v.x), "f"(v.y), "f"(v.z), "f"(v.w)
                 : "memory");
}

// ---------------------------------------------------------------------------
// Kernel 2: fused  h = x + agg;  out = x + relu(relu(h@W1+b1)@W2+b2)
// blockDim = 64. Thread j holds W1[:,j] and W2[:,j] in registers (loaded once,
// reused for NODES_PER_BLOCK nodes). The per-node 64-vector is broadcast
// through shared memory as float4s (conflict-free broadcast reads).
// Also zeroes g_agg behind itself.
// ---------------------------------------------------------------------------
__global__ void __launch_bounds__(64) gin_mlp_kernel(
    const float* __restrict__ x,
    const float* __restrict__ W1,
    const float* __restrict__ b1,
    const float* __restrict__ W2,
    const float* __restrict__ b2,
    float* __restrict__ out,
    int n_nodes)
{
    __shared__ float h_sh[DIM];
    __shared__ float h1_sh[DIM];

    const int j = threadIdx.x;

    // Per-thread weight columns in registers.
    float w1[DIM], w2[DIM];
#pragma unroll
    for (int k = 0; k < DIM; k++) {
        w1[k] = __ldg(W1 + k * DIM + j);
        w2[k] = __ldg(W2 + k * DIM + j);
    }
    const float b1j = __ldg(b1 + j);
    const float b2j = __ldg(b2 + j);

    const int node0 = blockIdx.x * NODES_PER_BLOCK;

    for (int t = 0; t < NODES_PER_BLOCK; t++) {
        const int node = node0 + t;
        if (node >= n_nodes) break;
        const size_t base = (size_t)node * DIM;

        const float xj = x[base + j];
        h_sh[j] = xj + g_agg[base + j];
        g_agg[base + j] = 0.0f;              // restore scratch for next replay
        __syncthreads();

        // layer 1: acc = b1[j] + sum_k h[k] * W1[k][j]
        float acc = b1j;
        const float4* h4 = reinterpret_cast<const float4*>(h_sh);
#pragma unroll
        for (int k = 0; k < DIM / 4; k++) {
            const float4 v = h4[k];
            acc = fmaf(v.x, w1[4 * k + 0], acc);
            acc = fmaf(v.y, w1[4 * k + 1], acc);
            acc = fmaf(v.z, w1[4 * k + 2], acc);
            acc = fmaf(v.w, w1[4 * k + 3], acc);
        }
        h1_sh[j] = fmaxf(acc, 0.0f);
        __syncthreads();

        // layer 2: acc2 = b2[j] + sum_k h1[k] * W2[k][j]
        float acc2 = b2j;
        const float4* g4 = reinterpret_cast<const float4*>(h1_sh);
#pragma unroll
        for (int k = 0; k < DIM / 4; k++) {
            const float4 v = g4[k];
            acc2 = fmaf(v.x, w2[4 * k + 0], acc2);
            acc2 = fmaf(v.y, w2[4 * k + 1], acc2);
            acc2 = fmaf(v.z, w2[4 * k + 2], acc2);
            acc2 = fmaf(v.w, w2[4 * k + 3], acc2);
        }
        out[base + j] = xj + fmaxf(acc2, 0.0f);
        // barrier before next iteration overwrites h_sh
        __syncthreads();
    }
}

// ---------------------------------------------------------------------------
// Launch
// ---------------------------------------------------------------------------
extern "C" void kernel_launch(void* const* d_in, const int* in_sizes, int n_in,
                              void* d_out, int out_size)
{
    const float* x  = (const float*)d_in[0];
    const int*   ei = (const int*)  d_in[1];
    const float* W1 = (const float*)d_in[2];
    const float* b1 = (const float*)d_in[3];
    const float* W2 = (const float*)d_in[4];
    const float* b2 = (const float*)d_in[5];
    float* out = (float*)d_out;

    const int n_nodes = in_sizes[0] / DIM;
    const int n_edges = in_sizes[1] / 2;

    // Kernel 1: scatter-add (16 threads per edge)
    {
        long long total = (long long)n_edges * 16;
        int threads = 256;
        int blocks = (int)((total + threads - 1) / threads);
        gin_scatter_kernel<<<blocks, threads>>>(ei, x, n_edges);
    }

    // Kernel 2: fused MLP + residual (+ agg zeroing)
    {
        int blocks = (n_nodes + NODES_PER_BLOCK - 1) / NODES_PER_BLOCK;
        gin_mlp_kernel<<<blocks, 64>>>(x, W1, b1, W2, b2, out, n_nodes);
    }
}

// round 3
// speedup vs baseline: 1.0017x; 1.0017x over previous
#include <cuda_runtime.h>
#include <cstddef>

#define DIM 64
#define MAX_NODES 100000
#define NODES_PER_BLOCK 16

// Scratch aggregate buffer. __device__ globals are zero-initialized at module
// load, and the MLP kernel re-zeroes every element it reads, so the buffer is
// all-zero again at the end of every kernel_launch invocation (graph-replay safe).
__device__ float g_agg[(size_t)MAX_NODES * DIM];

// ---------------------------------------------------------------------------
// Kernel 1: edge scatter-add.  One thread per (edge, 16B chunk): 16 threads/edge.
// x[src] rows are 256B and hit L2 (x = 25.6MB < 126MB L2). The adds go through
// the L2 atomic ALUs via vector red (4 floats / op).
// ---------------------------------------------------------------------------
__global__ void __launch_bounds__(256) gin_scatter_kernel(
    const int* __restrict__ edge_index,   // [2, E] flat: src = [0,E), dst = [E,2E)
    const float* __restrict__ x,
    int n_edges)
{
    int gid = blockIdx.x * blockDim.x + threadIdx.x;
    int e = gid >> 4;
    if (e >= n_edges) return;
    int c = gid & 15;

    int src = __ldg(edge_index + e);
    int dst = __ldg(edge_index + n_edges + e);

    const float4 v = *reinterpret_cast<const float4*>(x + (size_t)src * DIM + c * 4);
    float* p = g_agg + (size_t)dst * DIM + c * 4;
    asm volatile("red.global.add.v4.f32 [%0], {%1, %2, %3, %4};"
                 :: "l"(p), "f"(v.x), "f"(v.y), "f"(v.z), "f"(v.w)
                 : "memory");
}

// ---------------------------------------------------------------------------
// Kernel 2: fused  h = x + agg;  out = x + relu(relu(h@W1+b1)@W2+b2)
// blockDim = 64. Thread j holds W1[:,j] and W2[:,j] in registers (loaded once,
// reused for NODES_PER_BLOCK nodes). The per-node 64-vector is broadcast
// through shared memory as float4s (conflict-free broadcast reads).
// Also zeroes g_agg behind itself.
// ---------------------------------------------------------------------------
__global__ void __launch_bounds__(64) gin_mlp_kernel(
    const float* __restrict__ x,
    const float* __restrict__ W1,
    const float* __restrict__ b1,
    const float* __restrict__ W2,
    const float* __restrict__ b2,
    float* __restrict__ out,
    int n_nodes)
{
    __shared__ float h_sh[DIM];
    __shared__ float h1_sh[DIM];

    const int j = threadIdx.x;

    // Per-thread weight columns in registers.
    float w1[DIM], w2[DIM];
#pragma unroll
    for (int k = 0; k < DIM; k++) {
        w1[k] = __ldg(W1 + k * DIM + j);
        w2[k] = __ldg(W2 + k * DIM + j);
    }
    const float b1j = __ldg(b1 + j);
    const float b2j = __ldg(b2 + j);

    const int node0 = blockIdx.x * NODES_PER_BLOCK;

    for (int t = 0; t < NODES_PER_BLOCK; t++) {
        const int node = node0 + t;
        if (node >= n_nodes) break;
        const size_t base = (size_t)node * DIM;

        const float xj = x[base + j];
        h_sh[j] = xj + g_agg[base + j];
        g_agg[base + j] = 0.0f;              // restore scratch for next replay
        __syncthreads();

        // layer 1: acc = b1[j] + sum_k h[k] * W1[k][j]
        float acc = b1j;
        const float4* h4 = reinterpret_cast<const float4*>(h_sh);
#pragma unroll
        for (int k = 0; k < DIM / 4; k++) {
            const float4 v = h4[k];
            acc = fmaf(v.x, w1[4 * k + 0], acc);
            acc = fmaf(v.y, w1[4 * k + 1], acc);
            acc = fmaf(v.z, w1[4 * k + 2], acc);
            acc = fmaf(v.w, w1[4 * k + 3], acc);
        }
        h1_sh[j] = fmaxf(acc, 0.0f);
        __syncthreads();

        // layer 2: acc2 = b2[j] + sum_k h1[k] * W2[k][j]
        float acc2 = b2j;
        const float4* g4 = reinterpret_cast<const float4*>(h1_sh);
#pragma unroll
        for (int k = 0; k < DIM / 4; k++) {
            const float4 v = g4[k];
            acc2 = fmaf(v.x, w2[4 * k + 0], acc2);
            acc2 = fmaf(v.y, w2[4 * k + 1], acc2);
            acc2 = fmaf(v.z, w2[4 * k + 2], acc2);
            acc2 = fmaf(v.w, w2[4 * k + 3], acc2);
        }
        out[base + j] = xj + fmaxf(acc2, 0.0f);
        // barrier before next iteration overwrites h_sh
        __syncthreads();
    }
}

// ---------------------------------------------------------------------------
// Launch
// ---------------------------------------------------------------------------
extern "C" void kernel_launch(void* const* d_in, const int* in_sizes, int n_in,
                              void* d_out, int out_size)
{
    const float* x  = (const float*)d_in[0];
    const int*   ei = (const int*)  d_in[1];
    const float* W1 = (const float*)d_in[2];
    const float* b1 = (const float*)d_in[3];
    const float* W2 = (const float*)d_in[4];
    const float* b2 = (const float*)d_in[5];
    float* out = (float*)d_out;

    const int n_nodes = in_sizes[0] / DIM;
    const int n_edges = in_sizes[1] / 2;

    // Kernel 1: scatter-add (16 threads per edge)
    {
        long long total = (long long)n_edges * 16;
        int threads = 256;
        int blocks = (int)((total + threads - 1) / threads);
        gin_scatter_kernel<<<blocks, threads>>>(ei, x, n_edges);
    }

    // Kernel 2: fused MLP + residual (+ agg zeroing)
    {
        int blocks = (n_nodes + NODES_PER_BLOCK - 1) / NODES_PER_BLOCK;
        gin_mlp_kernel<<<blocks, 64>>>(x, W1, b1, W2, b2, out, n_nodes);
    }
}

// round 4
// speedup vs baseline: 1.0032x; 1.0014x over previous
#include <cuda_runtime.h>
#include <cstddef>

#define DIM 64
#define MAX_NODES 100000
#define NODES_PER_BLOCK 16

// Scratch aggregate buffer. __device__ globals are zero-initialized at module
// load, and the MLP kernel re-zeroes every element it reads, so the buffer is
// all-zero again at the end of every kernel_launch invocation (graph-replay safe).
__device__ float g_agg[(size_t)MAX_NODES * DIM];

// ---------------------------------------------------------------------------
// Kernel 1: edge scatter-add.  One thread per (edge, 16B chunk): 16 threads/edge.
// x[src] rows are 256B and hit L2 (x = 25.6MB < 126MB L2). The adds go through
// the L2 atomic ALUs via vector red (4 floats / op).
// ---------------------------------------------------------------------------
__global__ void __launch_bounds__(256) gin_scatter_kernel(
    const int* __restrict__ edge_index,   // [2, E] flat: src = [0,E), dst = [E,2E)
    const float* __restrict__ x,
    int n_edges)
{
    int gid = blockIdx.x * blockDim.x + threadIdx.x;
    int e = gid >> 4;
    if (e >= n_edges) return;
    int c = gid & 15;

    int src = __ldg(edge_index + e);
    int dst = __ldg(edge_index + n_edges + e);

    const float4 v = *reinterpret_cast<const float4*>(x + (size_t)src * DIM + c * 4);
    float* p = g_agg + (size_t)dst * DIM + c * 4;
    asm volatile("red.global.add.v4.f32 [%0], {%1, %2, %3, %4};"
                 :: "l"(p), "f"(v.x), "f"(v.y), "f"(v.z), "f"(v.w)
                 : "memory");
}

// ---------------------------------------------------------------------------
// Kernel 2: fused  h = x + agg;  out = x + relu(relu(h@W1+b1)@W2+b2)
// blockDim = 64. Thread j holds W1[:,j] and W2[:,j] in registers (loaded once,
// reused for NODES_PER_BLOCK nodes). The per-node 64-vector is broadcast
// through shared memory as float4s (conflict-free broadcast reads).
// Also zeroes g_agg behind itself.
// ---------------------------------------------------------------------------
__global__ void __launch_bounds__(64) gin_mlp_kernel(
    const float* __restrict__ x,
    const float* __restrict__ W1,
    const float* __restrict__ b1,
    const float* __restrict__ W2,
    const float* __restrict__ b2,
    float* __restrict__ out,
    int n_nodes)
{
    __shared__ float h_sh[DIM];
    __shared__ float h1_sh[DIM];

    const int j = threadIdx.x;

    // Per-thread weight columns in registers.
    float w1[DIM], w2[DIM];
#pragma unroll
    for (int k = 0; k < DIM; k++) {
        w1[k] = __ldg(W1 + k * DIM + j);
        w2[k] = __ldg(W2 + k * DIM + j);
    }
    const float b1j = __ldg(b1 + j);
    const float b2j = __ldg(b2 + j);

    const int node0 = blockIdx.x * NODES_PER_BLOCK;

    for (int t = 0; t < NODES_PER_BLOCK; t++) {
        const int node = node0 + t;
        if (node >= n_nodes) break;
        const size_t base = (size_t)node * DIM;

        const float xj = x[base + j];
        h_sh[j] = xj + g_agg[base + j];
        g_agg[base + j] = 0.0f;              // restore scratch for next replay
        __syncthreads();

        // layer 1: acc = b1[j] + sum_k h[k] * W1[k][j]
        float acc = b1j;
        const float4* h4 = reinterpret_cast<const float4*>(h_sh);
#pragma unroll
        for (int k = 0; k < DIM / 4; k++) {
            const float4 v = h4[k];
            acc = fmaf(v.x, w1[4 * k + 0], acc);
            acc = fmaf(v.y, w1[4 * k + 1], acc);
            acc = fmaf(v.z, w1[4 * k + 2], acc);
            acc = fmaf(v.w, w1[4 * k + 3], acc);
        }
        h1_sh[j] = fmaxf(acc, 0.0f);
        __syncthreads();

        // layer 2: acc2 = b2[j] + sum_k h1[k] * W2[k][j]
        float acc2 = b2j;
        const float4* g4 = reinterpret_cast<const float4*>(h1_sh);
#pragma unroll
        for (int k = 0; k < DIM / 4; k++) {
            const float4 v = g4[k];
            acc2 = fmaf(v.x, w2[4 * k + 0], acc2);
            acc2 = fmaf(v.y, w2[4 * k + 1], acc2);
            acc2 = fmaf(v.z, w2[4 * k + 2], acc2);
            acc2 = fmaf(v.w, w2[4 * k + 3], acc2);
        }
        out[base + j] = xj + fmaxf(acc2, 0.0f);
        // barrier before next iteration overwrites h_sh
        __syncthreads();
    }
}

// ---------------------------------------------------------------------------
// Launch
// ---------------------------------------------------------------------------
extern "C" void kernel_launch(void* const* d_in, const int* in_sizes, int n_in,
                              void* d_out, int out_size)
{
    const float* x  = (const float*)d_in[0];
    const int*   ei = (const int*)  d_in[1];
    const float* W1 = (const float*)d_in[2];
    const float* b1 = (const float*)d_in[3];
    const float* W2 = (const float*)d_in[4];
    const float* b2 = (const float*)d_in[5];
    float* out = (float*)d_out;

    const int n_nodes = in_sizes[0] / DIM;
    const int n_edges = in_sizes[1] / 2;

    // Kernel 1: scatter-add (16 threads per edge)
    {
        long long total = (long long)n_edges * 16;
        int threads = 256;
        int blocks = (int)((total + threads - 1) / threads);
        gin_scatter_kernel<<<blocks, threads>>>(ei, x, n_edges);
    }

    // Kernel 2: fused MLP + residual (+ agg zeroing)
    {
        int blocks = (n_nodes + NODES_PER_BLOCK - 1) / NODES_PER_BLOCK;
        gin_mlp_kernel<<<blocks, 64>>>(x, W1, b1, W2, b2, out, n_nodes);
    }
}